// round 1
// baseline (speedup 1.0000x reference)
#include <cuda_runtime.h>

#define BQ   2
#define SEQ  2048
#define DIMC 1024
#define NH   16
#define DH   64
#define QKVC 3072
#define NROWS (BQ*SEQ)

// ---- device scratch (allocation-free rule: __device__ globals) ----
__device__ float g_xn[(size_t)NROWS * DIMC];            // 16 MB  layernormed x
__device__ float g_qkv[(size_t)NROWS * QKVC];           // 48 MB  [q | k | v] per row
__device__ float g_dots[(size_t)BQ * NH * SEQ * SEQ];   // 512 MB [b,h,i,j] (reused in place)
__device__ float g_ao[(size_t)BQ * NH * SEQ * DH];      // 16 MB  attention output [b,g,i,d]

// ============================================================ LayerNorm
__global__ void ln_kernel(const float* __restrict__ x,
                          const float* __restrict__ gamma,
                          const float* __restrict__ beta) {
    int row = blockIdx.x;
    int t = threadIdx.x;
    const float4* xr = (const float4*)(x + (size_t)row * DIMC);
    float4 v = xr[t];
    float s = v.x + v.y + v.z + v.w;
    float q = v.x*v.x + v.y*v.y + v.z*v.z + v.w*v.w;
    __shared__ float s_sum[8], s_sq[8];
    #pragma unroll
    for (int o = 16; o > 0; o >>= 1) {
        s += __shfl_xor_sync(0xffffffffu, s, o);
        q += __shfl_xor_sync(0xffffffffu, q, o);
    }
    if ((t & 31) == 0) { s_sum[t >> 5] = s; s_sq[t >> 5] = q; }
    __syncthreads();
    if (t < 32) {
        float a = (t < 8) ? s_sum[t] : 0.f;
        float c = (t < 8) ? s_sq[t] : 0.f;
        #pragma unroll
        for (int o = 4; o > 0; o >>= 1) {
            a += __shfl_xor_sync(0xffffffffu, a, o);
            c += __shfl_xor_sync(0xffffffffu, c, o);
        }
        if (t == 0) { s_sum[0] = a; s_sq[0] = c; }
    }
    __syncthreads();
    float mean = s_sum[0] * (1.f / DIMC);
    float var  = s_sq[0] * (1.f / DIMC) - mean * mean;
    float rs = rsqrtf(var + 1e-5f);
    float4 gg = ((const float4*)gamma)[t];
    float4 bb = ((const float4*)beta)[t];
    float4 o;
    o.x = (v.x - mean) * rs * gg.x + bb.x;
    o.y = (v.y - mean) * rs * gg.y + bb.y;
    o.z = (v.z - mean) * rs * gg.z + bb.z;
    o.w = (v.w - mean) * rs * gg.w + bb.w;
    ((float4*)(g_xn + (size_t)row * DIMC))[t] = o;
}

// ============================================================ QKV projection
// g_qkv[4096,3072] = g_xn[4096,1024] @ [Wq | Wkv]
__global__ __launch_bounds__(256)
void proj_gemm_kernel(const float* __restrict__ Wq, const float* __restrict__ Wkv) {
    __shared__ float As[8][128];
    __shared__ float Bs[8][128];
    int t = threadIdx.x;
    int cb = blockIdx.x * 128;
    const float* Bp; int ldb;
    if (cb < 1024) { Bp = Wq; ldb = 1024; } else { Bp = Wkv; ldb = 2048; cb -= 1024; }
    int ar = t >> 1, ac = (t & 1) * 4;
    int br = t >> 5, bc = (t & 31) * 4;
    const float* Aptr = g_xn + (size_t)(blockIdx.y * 128 + ar) * DIMC + ac;
    const float* Bptr = Bp + (size_t)br * ldb + cb + bc;
    int tx = t & 15, ty = t >> 4;
    float acc[8][8];
    #pragma unroll
    for (int i = 0; i < 8; i++)
        #pragma unroll
        for (int j = 0; j < 8; j++) acc[i][j] = 0.f;
    for (int kk = 0; kk < DIMC; kk += 8) {
        float4 a = *(const float4*)Aptr; Aptr += 8;
        float4 b = *(const float4*)Bptr; Bptr += (size_t)8 * ldb;
        As[ac+0][ar] = a.x; As[ac+1][ar] = a.y; As[ac+2][ar] = a.z; As[ac+3][ar] = a.w;
        *(float4*)&Bs[br][bc] = b;
        __syncthreads();
        #pragma unroll
        for (int k = 0; k < 8; k++) {
            float rm[8], rn[8];
            *(float4*)&rm[0] = *(const float4*)&As[k][ty*8];
            *(float4*)&rm[4] = *(const float4*)&As[k][ty*8+4];
            *(float4*)&rn[0] = *(const float4*)&Bs[k][tx*8];
            *(float4*)&rn[4] = *(const float4*)&Bs[k][tx*8+4];
            #pragma unroll
            for (int i = 0; i < 8; i++)
                #pragma unroll
                for (int j = 0; j < 8; j++)
                    acc[i][j] = fmaf(rm[i], rn[j], acc[i][j]);
        }
        __syncthreads();
    }
    float* Cp = g_qkv + (size_t)(blockIdx.y*128 + ty*8) * QKVC + blockIdx.x*128 + tx*8;
    #pragma unroll
    for (int i = 0; i < 8; i++) {
        *(float4*)&Cp[(size_t)i*QKVC + 0] = make_float4(acc[i][0], acc[i][1], acc[i][2], acc[i][3]);
        *(float4*)&Cp[(size_t)i*QKVC + 4] = make_float4(acc[i][4], acc[i][5], acc[i][6], acc[i][7]);
    }
}

// ============================================================ S_h = scale * Q_h K_h^T (batched over b,h)
__global__ __launch_bounds__(256)
void qk_gemm_kernel() {
    __shared__ float As[8][128];
    __shared__ float Bs[8][128];
    int t = threadIdx.x;
    int z = blockIdx.z;              // b*16 + h
    int b = z >> 4, h = z & 15;
    const float* Qb = g_qkv + (size_t)b * SEQ * QKVC + h * DH;
    const float* Kb = Qb + 1024;
    int ar = t >> 1, ac = (t & 1) * 4;
    const float* Ap = Qb + (size_t)(blockIdx.y*128 + ar) * QKVC + ac;
    const float* Bp = Kb + (size_t)(blockIdx.x*128 + ar) * QKVC + ac;
    int tx = t & 15, ty = t >> 4;
    float acc[8][8];
    #pragma unroll
    for (int i = 0; i < 8; i++)
        #pragma unroll
        for (int j = 0; j < 8; j++) acc[i][j] = 0.f;
    for (int kk = 0; kk < DH; kk += 8) {
        float4 a  = *(const float4*)Ap; Ap += 8;
        float4 bv = *(const float4*)Bp; Bp += 8;
        As[ac+0][ar] = a.x;  As[ac+1][ar] = a.y;  As[ac+2][ar] = a.z;  As[ac+3][ar] = a.w;
        Bs[ac+0][ar] = bv.x; Bs[ac+1][ar] = bv.y; Bs[ac+2][ar] = bv.z; Bs[ac+3][ar] = bv.w;
        __syncthreads();
        #pragma unroll
        for (int k = 0; k < 8; k++) {
            float rm[8], rn[8];
            *(float4*)&rm[0] = *(const float4*)&As[k][ty*8];
            *(float4*)&rm[4] = *(const float4*)&As[k][ty*8+4];
            *(float4*)&rn[0] = *(const float4*)&Bs[k][tx*8];
            *(float4*)&rn[4] = *(const float4*)&Bs[k][tx*8+4];
            #pragma unroll
            for (int i = 0; i < 8; i++)
                #pragma unroll
                for (int j = 0; j < 8; j++)
                    acc[i][j] = fmaf(rm[i], rn[j], acc[i][j]);
        }
        __syncthreads();
    }
    const float scale = 0.125f;  // 64^-0.5
    float* Cp = g_dots + ((size_t)z*SEQ + blockIdx.y*128 + ty*8) * SEQ + blockIdx.x*128 + tx*8;
    #pragma unroll
    for (int i = 0; i < 8; i++) {
        *(float4*)&Cp[(size_t)i*SEQ + 0] =
            make_float4(acc[i][0]*scale, acc[i][1]*scale, acc[i][2]*scale, acc[i][3]*scale);
        *(float4*)&Cp[(size_t)i*SEQ + 4] =
            make_float4(acc[i][4]*scale, acc[i][5]*scale, acc[i][6]*scale, acc[i][7]*scale);
    }
}

// ============================================================ pre-mix -> softmax -> post-mix, in place
// one block per (b, i): holds all 16 heads' full rows (16*2048 f32 = 128 KB dyn smem)
__global__ __launch_bounds__(256)
void mixsoftmax_kernel(const float* __restrict__ mix_pre, const float* __restrict__ mix_post) {
    extern __shared__ float srow[];          // [NH][SEQ]
    __shared__ float mp[256], mq[256];
    __shared__ float red[NH][8];
    __shared__ float mg[NH], linv[NH];
    int t = threadIdx.x;
    int b = blockIdx.x >> 11;
    int i = blockIdx.x & (SEQ - 1);
    mp[t] = mix_pre[t];
    mq[t] = mix_post[t];
    size_t base = ((size_t)(b * NH) * SEQ + i) * SEQ;  // [b,0,i,0]; +h*SEQ*SEQ per head
    for (int h = 0; h < NH; h++) {
        const float4* src = (const float4*)(g_dots + base + (size_t)h * SEQ * SEQ);
        float4* dst = (float4*)(srow + h * SEQ);
        for (int j = t; j < SEQ/4; j += 256) dst[j] = src[j];
    }
    __syncthreads();
    // pre-mix (in place, h planes -> g planes), per-thread column ownership
    float tmax[NH];
    #pragma unroll
    for (int g = 0; g < NH; g++) tmax[g] = -3.4e38f;
    for (int j = t; j < SEQ; j += 256) {
        float sh[NH];
        #pragma unroll
        for (int h = 0; h < NH; h++) sh[h] = srow[h*SEQ + j];
        #pragma unroll
        for (int g = 0; g < NH; g++) {
            float v = 0.f;
            #pragma unroll
            for (int h = 0; h < NH; h++) v = fmaf(mp[h*NH + g], sh[h], v);
            srow[g*SEQ + j] = v;
            tmax[g] = fmaxf(tmax[g], v);
        }
    }
    int w = t >> 5, l = t & 31;
    #pragma unroll
    for (int g = 0; g < NH; g++) {
        float v = tmax[g];
        #pragma unroll
        for (int o = 16; o > 0; o >>= 1) v = fmaxf(v, __shfl_xor_sync(0xffffffffu, v, o));
        if (l == 0) red[g][w] = v;
    }
    __syncthreads();
    if (t < NH) {
        float v = red[t][0];
        #pragma unroll
        for (int w2 = 1; w2 < 8; w2++) v = fmaxf(v, red[t][w2]);
        mg[t] = v;
    }
    __syncthreads();
    // exp + rowsum
    float tsum[NH];
    #pragma unroll
    for (int g = 0; g < NH; g++) tsum[g] = 0.f;
    for (int j = t; j < SEQ; j += 256) {
        #pragma unroll
        for (int g = 0; g < NH; g++) {
            float e = __expf(srow[g*SEQ + j] - mg[g]);
            srow[g*SEQ + j] = e;
            tsum[g] += e;
        }
    }
    __syncthreads();
    #pragma unroll
    for (int g = 0; g < NH; g++) {
        float v = tsum[g];
        #pragma unroll
        for (int o = 16; o > 0; o >>= 1) v += __shfl_xor_sync(0xffffffffu, v, o);
        if (l == 0) red[g][w] = v;
    }
    __syncthreads();
    if (t < NH) {
        float v = 0.f;
        #pragma unroll
        for (int w2 = 0; w2 < 8; w2++) v += red[t][w2];
        linv[t] = 1.f / v;
    }
    __syncthreads();
    // post-mix on normalized probs, write back to global (in place)
    for (int j = t; j < SEQ; j += 256) {
        float ph[NH];
        #pragma unroll
        for (int h = 0; h < NH; h++) ph[h] = srow[h*SEQ + j] * linv[h];
        #pragma unroll
        for (int g = 0; g < NH; g++) {
            float v = 0.f;
            #pragma unroll
            for (int h = 0; h < NH; h++) v = fmaf(mq[h*NH + g], ph[h], v);
            g_dots[base + (size_t)g*SEQ*SEQ + j] = v;
        }
    }
}

// ============================================================ O_g = A'_g @ V_g (batched over b,g)
__global__ __launch_bounds__(256)
void av_gemm_kernel() {
    __shared__ float As[16][128];
    __shared__ float Bs[16][64];
    int t = threadIdx.x;
    int z = blockIdx.y;              // b*16 + g
    int b = z >> 4, g = z & 15;
    const float* Am = g_dots + (size_t)z * SEQ * SEQ;
    const float* Vb = g_qkv + (size_t)b * SEQ * QKVC + 2048 + g * DH;
    int ar = t >> 1, ac = (t & 1) * 8;
    int br = t >> 4, bc = (t & 15) * 4;
    int tx = t & 15, ty = t >> 4;
    float acc[8][4];
    #pragma unroll
    for (int i = 0; i < 8; i++)
        #pragma unroll
        for (int j = 0; j < 4; j++) acc[i][j] = 0.f;
    const float* Ap = Am + (size_t)(blockIdx.x*128 + ar) * SEQ + ac;
    const float* Bp = Vb + (size_t)br * QKVC + bc;
    for (int kk = 0; kk < SEQ; kk += 16) {
        float4 a0 = *(const float4*)Ap;
        float4 a1 = *(const float4*)(Ap + 4);
        Ap += 16;
        float4 bv = *(const float4*)Bp;
        Bp += (size_t)16 * QKVC;
        As[ac+0][ar] = a0.x; As[ac+1][ar] = a0.y; As[ac+2][ar] = a0.z; As[ac+3][ar] = a0.w;
        As[ac+4][ar] = a1.x; As[ac+5][ar] = a1.y; As[ac+6][ar] = a1.z; As[ac+7][ar] = a1.w;
        *(float4*)&Bs[br][bc] = bv;
        __syncthreads();
        #pragma unroll
        for (int k = 0; k < 16; k++) {
            float rm[8], rn[4];
            *(float4*)&rm[0] = *(const float4*)&As[k][ty*8];
            *(float4*)&rm[4] = *(const float4*)&As[k][ty*8+4];
            *(float4*)&rn[0] = *(const float4*)&Bs[k][tx*4];
            #pragma unroll
            for (int i = 0; i < 8; i++)
                #pragma unroll
                for (int j = 0; j < 4; j++)
                    acc[i][j] = fmaf(rm[i], rn[j], acc[i][j]);
        }
        __syncthreads();
    }
    float* Cp = g_ao + ((size_t)z*SEQ + blockIdx.x*128 + ty*8) * DH + tx*4;
    #pragma unroll
    for (int i = 0; i < 8; i++)
        *(float4*)&Cp[(size_t)i*DH] = make_float4(acc[i][0], acc[i][1], acc[i][2], acc[i][3]);
}

// ============================================================ out = O @ Wout + bout
// O logical [row=(b,i), col=(g,d)] stored as g_ao[b,g,i,d]
__global__ __launch_bounds__(256)
void out_gemm_kernel(const float* __restrict__ Wout, const float* __restrict__ bout,
                     float* __restrict__ out) {
    __shared__ float As[8][128];
    __shared__ float Bs[8][128];
    int t = threadIdx.x;
    int ar = t >> 1, ac = (t & 1) * 4;
    int br = t >> 5, bc = (t & 31) * 4;
    int tx = t & 15, ty = t >> 4;
    int row0 = blockIdx.y * 128 + ar;
    int b = row0 >> 11, i = row0 & (SEQ - 1);
    const float* Ab = g_ao + (((size_t)b * NH) * SEQ + i) * DH;   // + (k>>6)*SEQ*DH + (k&63)
    const float* Bptr = Wout + (size_t)br * DIMC + blockIdx.x*128 + bc;
    float acc[8][8];
    #pragma unroll
    for (int ii = 0; ii < 8; ii++)
        #pragma unroll
        for (int j = 0; j < 8; j++) acc[ii][j] = 0.f;
    for (int kk = 0; kk < DIMC; kk += 8) {
        int k0 = kk + ac;
        float4 a = *(const float4*)(Ab + (size_t)(k0 >> 6) * SEQ * DH + (k0 & 63));
        float4 bv = *(const float4*)Bptr; Bptr += (size_t)8 * DIMC;
        As[ac+0][ar] = a.x; As[ac+1][ar] = a.y; As[ac+2][ar] = a.z; As[ac+3][ar] = a.w;
        *(float4*)&Bs[br][bc] = bv;
        __syncthreads();
        #pragma unroll
        for (int k = 0; k < 8; k++) {
            float rm[8], rn[8];
            *(float4*)&rm[0] = *(const float4*)&As[k][ty*8];
            *(float4*)&rm[4] = *(const float4*)&As[k][ty*8+4];
            *(float4*)&rn[0] = *(const float4*)&Bs[k][tx*8];
            *(float4*)&rn[4] = *(const float4*)&Bs[k][tx*8+4];
            #pragma unroll
            for (int ii = 0; ii < 8; ii++)
                #pragma unroll
                for (int j = 0; j < 8; j++)
                    acc[ii][j] = fmaf(rm[ii], rn[j], acc[ii][j]);
        }
        __syncthreads();
    }
    int col0 = blockIdx.x*128 + tx*8;
    float bias[8];
    #pragma unroll
    for (int j = 0; j < 8; j++) bias[j] = bout[col0 + j];
    float* Cp = out + (size_t)(blockIdx.y*128 + ty*8) * DIMC + col0;
    #pragma unroll
    for (int ii = 0; ii < 8; ii++) {
        *(float4*)&Cp[(size_t)ii*DIMC + 0] =
            make_float4(acc[ii][0]+bias[0], acc[ii][1]+bias[1], acc[ii][2]+bias[2], acc[ii][3]+bias[3]);
        *(float4*)&Cp[(size_t)ii*DIMC + 4] =
            make_float4(acc[ii][4]+bias[4], acc[ii][5]+bias[5], acc[ii][6]+bias[6], acc[ii][7]+bias[7]);
    }
}

// ============================================================ launch
extern "C" void kernel_launch(void* const* d_in, const int* in_sizes, int n_in,
                              void* d_out, int out_size) {
    const float* x       = (const float*)d_in[0];
    const float* ln_g    = (const float*)d_in[1];
    const float* ln_b    = (const float*)d_in[2];
    const float* Wq      = (const float*)d_in[3];
    const float* Wkv     = (const float*)d_in[4];
    const float* mixpre  = (const float*)d_in[5];
    const float* mixpost = (const float*)d_in[6];
    const float* Wout    = (const float*)d_in[7];
    const float* bout    = (const float*)d_in[8];
    float* out = (float*)d_out;

    cudaFuncSetAttribute(mixsoftmax_kernel,
                         cudaFuncAttributeMaxDynamicSharedMemorySize, NH * SEQ * 4);

    ln_kernel<<<NROWS, 256>>>(x, ln_g, ln_b);
    proj_gemm_kernel<<<dim3(24, 32), 256>>>(Wq, Wkv);
    qk_gemm_kernel<<<dim3(16, 16, 32), 256>>>();
    mixsoftmax_kernel<<<BQ * SEQ, 256, NH * SEQ * 4>>>(mixpre, mixpost);
    av_gemm_kernel<<<dim3(16, 32), 256>>>();
    out_gemm_kernel<<<dim3(8, 32), 256>>>(Wout, bout, out);
}

// round 2
// speedup vs baseline: 1.5354x; 1.5354x over previous
#include <cuda_runtime.h>
#include <cstdint>

#define BQ   2
#define SEQ  2048
#define DIMC 1024
#define NH   16
#define DH   64
#define QKVC 3072
#define NROWS (BQ*SEQ)

// ---- device scratch ----
__device__ float g_xn[(size_t)NROWS * DIMC];            // 16 MB
__device__ float g_qkv[(size_t)NROWS * QKVC];           // 48 MB  [q | k | v]
__device__ float g_dots[(size_t)BQ * NH * SEQ * SEQ];   // 512 MB
__device__ float g_ao[(size_t)BQ * NH * SEQ * DH];      // 16 MB  [b,g,i,d]

__device__ __forceinline__ uint32_t f2tf32(float f) {
    uint32_t u; asm("cvt.rna.tf32.f32 %0, %1;" : "=r"(u) : "f"(f)); return u;
}

#define MMA_TF32(c, a, b) \
    asm volatile("mma.sync.aligned.m16n8k8.row.col.f32.tf32.tf32.f32 " \
        "{%0,%1,%2,%3}, {%4,%5,%6,%7}, {%8,%9}, {%0,%1,%2,%3};" \
        : "+f"((c)[0]), "+f"((c)[1]), "+f"((c)[2]), "+f"((c)[3]) \
        : "r"((a)[0]), "r"((a)[1]), "r"((a)[2]), "r"((a)[3]), \
          "r"((b)[0]), "r"((b)[1]))

// ============================================================ LayerNorm
__global__ void ln_kernel(const float* __restrict__ x,
                          const float* __restrict__ gamma,
                          const float* __restrict__ beta) {
    int row = blockIdx.x;
    int t = threadIdx.x;
    const float4* xr = (const float4*)(x + (size_t)row * DIMC);
    float4 v = xr[t];
    float s = v.x + v.y + v.z + v.w;
    float q = v.x*v.x + v.y*v.y + v.z*v.z + v.w*v.w;
    __shared__ float s_sum[8], s_sq[8];
    #pragma unroll
    for (int o = 16; o > 0; o >>= 1) {
        s += __shfl_xor_sync(0xffffffffu, s, o);
        q += __shfl_xor_sync(0xffffffffu, q, o);
    }
    if ((t & 31) == 0) { s_sum[t >> 5] = s; s_sq[t >> 5] = q; }
    __syncthreads();
    if (t < 32) {
        float a = (t < 8) ? s_sum[t] : 0.f;
        float c = (t < 8) ? s_sq[t] : 0.f;
        #pragma unroll
        for (int o = 4; o > 0; o >>= 1) {
            a += __shfl_xor_sync(0xffffffffu, a, o);
            c += __shfl_xor_sync(0xffffffffu, c, o);
        }
        if (t == 0) { s_sum[0] = a; s_sq[0] = c; }
    }
    __syncthreads();
    float mean = s_sum[0] * (1.f / DIMC);
    float var  = s_sq[0] * (1.f / DIMC) - mean * mean;
    float rs = rsqrtf(var + 1e-5f);
    float4 gg = ((const float4*)gamma)[t];
    float4 bb = ((const float4*)beta)[t];
    float4 o;
    o.x = (v.x - mean) * rs * gg.x + bb.x;
    o.y = (v.y - mean) * rs * gg.y + bb.y;
    o.z = (v.z - mean) * rs * gg.z + bb.z;
    o.w = (v.w - mean) * rs * gg.w + bb.w;
    ((float4*)(g_xn + (size_t)row * DIMC))[t] = o;
}

// ============================================================ QKV projection (TF32 MMA)
// g_qkv[4096,3072] = g_xn[4096,1024] @ [Wq | Wkv]
__global__ __launch_bounds__(256)
void proj_mma_kernel(const float* __restrict__ Wq, const float* __restrict__ Wkv) {
    __shared__ uint32_t As[16][136];   // As[k][m]
    __shared__ uint32_t Bs[16][136];   // Bs[k][n]
    int t = threadIdx.x, lane = t & 31, w = t >> 5;
    int wm = (w & 1) * 64, wn = (w >> 1) * 32;
    int cb = blockIdx.x * 128;
    const float* Bp; int ldb;
    if (cb < 1024) { Bp = Wq; ldb = 1024; } else { Bp = Wkv; ldb = 2048; cb -= 1024; }
    int m0 = blockIdx.y * 128;
    int sa_m = t >> 1, sa_k = (t & 1) * 8;
    int sb_k = t >> 4, sb_n = (t & 15) * 8;
    const float* Aptr = g_xn + (size_t)(m0 + sa_m) * DIMC + sa_k;
    const float* Bptr = Bp + (size_t)sb_k * ldb + cb + sb_n;
    float c[4][4][4] = {};
    for (int kk = 0; kk < DIMC; kk += 16) {
        float4 a0 = *(const float4*)Aptr;
        float4 a1 = *(const float4*)(Aptr + 4);
        Aptr += 16;
        float4 b0 = *(const float4*)Bptr;
        float4 b1 = *(const float4*)(Bptr + 4);
        Bptr += (size_t)16 * ldb;
        As[sa_k+0][sa_m] = f2tf32(a0.x); As[sa_k+1][sa_m] = f2tf32(a0.y);
        As[sa_k+2][sa_m] = f2tf32(a0.z); As[sa_k+3][sa_m] = f2tf32(a0.w);
        As[sa_k+4][sa_m] = f2tf32(a1.x); As[sa_k+5][sa_m] = f2tf32(a1.y);
        As[sa_k+6][sa_m] = f2tf32(a1.z); As[sa_k+7][sa_m] = f2tf32(a1.w);
        *(uint4*)&Bs[sb_k][sb_n]   = make_uint4(f2tf32(b0.x), f2tf32(b0.y), f2tf32(b0.z), f2tf32(b0.w));
        *(uint4*)&Bs[sb_k][sb_n+4] = make_uint4(f2tf32(b1.x), f2tf32(b1.y), f2tf32(b1.z), f2tf32(b1.w));
        __syncthreads();
        #pragma unroll
        for (int ks = 0; ks < 2; ks++) {
            int kr = ks * 8 + (lane & 3);
            int mr = wm + (lane >> 2);
            int nr = wn + (lane >> 2);
            uint32_t af[4][4], bf[4][2];
            #pragma unroll
            for (int mt = 0; mt < 4; mt++) {
                af[mt][0] = As[kr][mr + mt*16];
                af[mt][1] = As[kr][mr + mt*16 + 8];
                af[mt][2] = As[kr+4][mr + mt*16];
                af[mt][3] = As[kr+4][mr + mt*16 + 8];
            }
            #pragma unroll
            for (int nt = 0; nt < 4; nt++) {
                bf[nt][0] = Bs[kr][nr + nt*8];
                bf[nt][1] = Bs[kr+4][nr + nt*8];
            }
            #pragma unroll
            for (int mt = 0; mt < 4; mt++)
                #pragma unroll
                for (int nt = 0; nt < 4; nt++)
                    MMA_TF32(c[mt][nt], af[mt], bf[nt]);
        }
        __syncthreads();
    }
    int col0 = blockIdx.x * 128 + wn + 2 * (lane & 3);
    int row0 = m0 + wm + (lane >> 2);
    #pragma unroll
    for (int mt = 0; mt < 4; mt++)
        #pragma unroll
        for (int nt = 0; nt < 4; nt++) {
            float* Cp = g_qkv + (size_t)(row0 + mt*16) * QKVC + col0 + nt*8;
            *(float2*)Cp = make_float2(c[mt][nt][0], c[mt][nt][1]);
            *(float2*)(Cp + (size_t)8 * QKVC) = make_float2(c[mt][nt][2], c[mt][nt][3]);
        }
}

// ============================================================ S_h = scale * Q_h K_h^T (TF32 MMA)
__global__ __launch_bounds__(256)
void qk_mma_kernel() {
    __shared__ uint32_t As[16][136];   // As[k][m] (Q transposed)
    __shared__ uint32_t Bs[16][136];   // Bs[k][n] (K transposed: k=d, n=j)
    int t = threadIdx.x, lane = t & 31, w = t >> 5;
    int wm = (w & 1) * 64, wn = (w >> 1) * 32;
    int z = blockIdx.z, b = z >> 4, h = z & 15;
    const float* Qb = g_qkv + (size_t)b * SEQ * QKVC + h * DH;
    const float* Kb = Qb + 1024;
    int m0 = blockIdx.y * 128, n0 = blockIdx.x * 128;
    int sm = t >> 1, sk = (t & 1) * 8;
    const float* Ap  = Qb + (size_t)(m0 + sm) * QKVC + sk;
    const float* Bp  = Kb + (size_t)(n0 + sm) * QKVC + sk;
    float c[4][4][4] = {};
    for (int kk = 0; kk < DH; kk += 16) {
        float4 a0 = *(const float4*)Ap;
        float4 a1 = *(const float4*)(Ap + 4);
        Ap += 16;
        float4 k0 = *(const float4*)Bp;
        float4 k1 = *(const float4*)(Bp + 4);
        Bp += 16;
        As[sk+0][sm] = f2tf32(a0.x); As[sk+1][sm] = f2tf32(a0.y);
        As[sk+2][sm] = f2tf32(a0.z); As[sk+3][sm] = f2tf32(a0.w);
        As[sk+4][sm] = f2tf32(a1.x); As[sk+5][sm] = f2tf32(a1.y);
        As[sk+6][sm] = f2tf32(a1.z); As[sk+7][sm] = f2tf32(a1.w);
        Bs[sk+0][sm] = f2tf32(k0.x); Bs[sk+1][sm] = f2tf32(k0.y);
        Bs[sk+2][sm] = f2tf32(k0.z); Bs[sk+3][sm] = f2tf32(k0.w);
        Bs[sk+4][sm] = f2tf32(k1.x); Bs[sk+5][sm] = f2tf32(k1.y);
        Bs[sk+6][sm] = f2tf32(k1.z); Bs[sk+7][sm] = f2tf32(k1.w);
        __syncthreads();
        #pragma unroll
        for (int ks = 0; ks < 2; ks++) {
            int kr = ks * 8 + (lane & 3);
            int mr = wm + (lane >> 2);
            int nr = wn + (lane >> 2);
            uint32_t af[4][4], bf[4][2];
            #pragma unroll
            for (int mt = 0; mt < 4; mt++) {
                af[mt][0] = As[kr][mr + mt*16];
                af[mt][1] = As[kr][mr + mt*16 + 8];
                af[mt][2] = As[kr+4][mr + mt*16];
                af[mt][3] = As[kr+4][mr + mt*16 + 8];
            }
            #pragma unroll
            for (int nt = 0; nt < 4; nt++) {
                bf[nt][0] = Bs[kr][nr + nt*8];
                bf[nt][1] = Bs[kr+4][nr + nt*8];
            }
            #pragma unroll
            for (int mt = 0; mt < 4; mt++)
                #pragma unroll
                for (int nt = 0; nt < 4; nt++)
                    MMA_TF32(c[mt][nt], af[mt], bf[nt]);
        }
        __syncthreads();
    }
    const float scale = 0.125f;
    int col0 = n0 + wn + 2 * (lane & 3);
    int row0 = m0 + wm + (lane >> 2);
    #pragma unroll
    for (int mt = 0; mt < 4; mt++)
        #pragma unroll
        for (int nt = 0; nt < 4; nt++) {
            float* Cp = g_dots + ((size_t)z * SEQ + row0 + mt*16) * SEQ + col0 + nt*8;
            *(float2*)Cp = make_float2(c[mt][nt][0]*scale, c[mt][nt][1]*scale);
            *(float2*)(Cp + (size_t)8 * SEQ) = make_float2(c[mt][nt][2]*scale, c[mt][nt][3]*scale);
        }
}

// ============================================================ pre-mix -> softmax -> post-mix, in place
__global__ __launch_bounds__(256)
void mixsoftmax_kernel(const float* __restrict__ mix_pre, const float* __restrict__ mix_post) {
    extern __shared__ float srow[];          // [NH][SEQ]
    __shared__ float mp[256], mq[256];
    __shared__ float red[NH][8];
    __shared__ float mg[NH], linv[NH];
    int t = threadIdx.x;
    int b = blockIdx.x >> 11;
    int i = blockIdx.x & (SEQ - 1);
    mp[t] = mix_pre[t];
    mq[t] = mix_post[t];
    size_t base = ((size_t)(b * NH) * SEQ + i) * SEQ;
    for (int h = 0; h < NH; h++) {
        const float4* src = (const float4*)(g_dots + base + (size_t)h * SEQ * SEQ);
        float4* dst = (float4*)(srow + h * SEQ);
        for (int j = t; j < SEQ/4; j += 256) dst[j] = src[j];
    }
    __syncthreads();
    float tmax[NH];
    #pragma unroll
    for (int g = 0; g < NH; g++) tmax[g] = -3.4e38f;
    for (int j = t; j < SEQ; j += 256) {
        float sh[NH];
        #pragma unroll
        for (int h = 0; h < NH; h++) sh[h] = srow[h*SEQ + j];
        #pragma unroll
        for (int g = 0; g < NH; g++) {
            float v = 0.f;
            #pragma unroll
            for (int h = 0; h < NH; h++) v = fmaf(mp[h*NH + g], sh[h], v);
            srow[g*SEQ + j] = v;
            tmax[g] = fmaxf(tmax[g], v);
        }
    }
    int w = t >> 5, l = t & 31;
    #pragma unroll
    for (int g = 0; g < NH; g++) {
        float v = tmax[g];
        #pragma unroll
        for (int o = 16; o > 0; o >>= 1) v = fmaxf(v, __shfl_xor_sync(0xffffffffu, v, o));
        if (l == 0) red[g][w] = v;
    }
    __syncthreads();
    if (t < NH) {
        float v = red[t][0];
        #pragma unroll
        for (int w2 = 1; w2 < 8; w2++) v = fmaxf(v, red[t][w2]);
        mg[t] = v;
    }
    __syncthreads();
    float tsum[NH];
    #pragma unroll
    for (int g = 0; g < NH; g++) tsum[g] = 0.f;
    for (int j = t; j < SEQ; j += 256) {
        #pragma unroll
        for (int g = 0; g < NH; g++) {
            float e = __expf(srow[g*SEQ + j] - mg[g]);
            srow[g*SEQ + j] = e;
            tsum[g] += e;
        }
    }
    __syncthreads();
    #pragma unroll
    for (int g = 0; g < NH; g++) {
        float v = tsum[g];
        #pragma unroll
        for (int o = 16; o > 0; o >>= 1) v += __shfl_xor_sync(0xffffffffu, v, o);
        if (l == 0) red[g][w] = v;
    }
    __syncthreads();
    if (t < NH) {
        float v = 0.f;
        #pragma unroll
        for (int w2 = 0; w2 < 8; w2++) v += red[t][w2];
        linv[t] = 1.f / v;
    }
    __syncthreads();
    for (int j = t; j < SEQ; j += 256) {
        float ph[NH];
        #pragma unroll
        for (int h = 0; h < NH; h++) ph[h] = srow[h*SEQ + j] * linv[h];
        #pragma unroll
        for (int g = 0; g < NH; g++) {
            float v = 0.f;
            #pragma unroll
            for (int h = 0; h < NH; h++) v = fmaf(mq[h*NH + g], ph[h], v);
            g_dots[base + (size_t)g*SEQ*SEQ + j] = v;
        }
    }
}

// ============================================================ O_g = A'_g @ V_g (TF32 MMA)
// block 128x64, warps 4(m) x 2(n), warp tile 32x32
__global__ __launch_bounds__(256)
void av_mma_kernel() {
    __shared__ uint32_t As[16][136];   // As[k][m] (probs transposed)
    __shared__ uint32_t Bs[16][72];    // Bs[k][n] (V direct)
    int t = threadIdx.x, lane = t & 31, w = t >> 5;
    int wm = (w & 3) * 32, wn = (w >> 2) * 32;
    int z = blockIdx.y, b = z >> 4, g = z & 15;
    const float* Am = g_dots + (size_t)z * SEQ * SEQ;
    const float* Vb = g_qkv + (size_t)b * SEQ * QKVC + 2048 + g * DH;
    int m0 = blockIdx.x * 128;
    int sm = t >> 1, sk = (t & 1) * 8;
    int bk = t >> 4, bn = (t & 15) * 4;
    const float* Ap = Am + (size_t)(m0 + sm) * SEQ + sk;
    const float* Bp = Vb + (size_t)bk * QKVC + bn;
    float c[2][4][4] = {};
    for (int kk = 0; kk < SEQ; kk += 16) {
        float4 a0 = *(const float4*)Ap;
        float4 a1 = *(const float4*)(Ap + 4);
        Ap += 16;
        float4 bv = *(const float4*)Bp;
        Bp += (size_t)16 * QKVC;
        As[sk+0][sm] = f2tf32(a0.x); As[sk+1][sm] = f2tf32(a0.y);
        As[sk+2][sm] = f2tf32(a0.z); As[sk+3][sm] = f2tf32(a0.w);
        As[sk+4][sm] = f2tf32(a1.x); As[sk+5][sm] = f2tf32(a1.y);
        As[sk+6][sm] = f2tf32(a1.z); As[sk+7][sm] = f2tf32(a1.w);
        *(uint4*)&Bs[bk][bn] = make_uint4(f2tf32(bv.x), f2tf32(bv.y), f2tf32(bv.z), f2tf32(bv.w));
        __syncthreads();
        #pragma unroll
        for (int ks = 0; ks < 2; ks++) {
            int kr = ks * 8 + (lane & 3);
            int mr = wm + (lane >> 2);
            int nr = wn + (lane >> 2);
            uint32_t af[2][4], bf[4][2];
            #pragma unroll
            for (int mt = 0; mt < 2; mt++) {
                af[mt][0] = As[kr][mr + mt*16];
                af[mt][1] = As[kr][mr + mt*16 + 8];
                af[mt][2] = As[kr+4][mr + mt*16];
                af[mt][3] = As[kr+4][mr + mt*16 + 8];
            }
            #pragma unroll
            for (int nt = 0; nt < 4; nt++) {
                bf[nt][0] = Bs[kr][nr + nt*8];
                bf[nt][1] = Bs[kr+4][nr + nt*8];
            }
            #pragma unroll
            for (int mt = 0; mt < 2; mt++)
                #pragma unroll
                for (int nt = 0; nt < 4; nt++)
                    MMA_TF32(c[mt][nt], af[mt], bf[nt]);
        }
        __syncthreads();
    }
    int col0 = wn + 2 * (lane & 3);
    int row0 = m0 + wm + (lane >> 2);
    #pragma unroll
    for (int mt = 0; mt < 2; mt++)
        #pragma unroll
        for (int nt = 0; nt < 4; nt++) {
            float* Cp = g_ao + ((size_t)z * SEQ + row0 + mt*16) * DH + col0 + nt*8;
            *(float2*)Cp = make_float2(c[mt][nt][0], c[mt][nt][1]);
            *(float2*)(Cp + (size_t)8 * DH) = make_float2(c[mt][nt][2], c[mt][nt][3]);
        }
}

// ============================================================ out = O @ Wout + bout (TF32 MMA)
__global__ __launch_bounds__(256)
void out_mma_kernel(const float* __restrict__ Wout, const float* __restrict__ bout,
                    float* __restrict__ out) {
    __shared__ uint32_t As[16][136];
    __shared__ uint32_t Bs[16][136];
    int t = threadIdx.x, lane = t & 31, w = t >> 5;
    int wm = (w & 1) * 64, wn = (w >> 1) * 32;
    int m0 = blockIdx.y * 128, n0 = blockIdx.x * 128;
    int sa_m = t >> 1, sa_k = (t & 1) * 8;
    int sb_k = t >> 4, sb_n = (t & 15) * 8;
    int row = m0 + sa_m;
    int bb = row >> 11, ii = row & (SEQ - 1);
    const float* Bptr = Wout + (size_t)sb_k * DIMC + n0 + sb_n;
    float c[4][4][4] = {};
    for (int kk = 0; kk < DIMC; kk += 16) {
        int k = kk + sa_k;
        int gh = k >> 6, d = k & 63;
        const float* Ap = g_ao + ((size_t)(bb * NH + gh) * SEQ + ii) * DH + d;
        float4 a0 = *(const float4*)Ap;
        float4 a1 = *(const float4*)(Ap + 4);
        float4 b0 = *(const float4*)Bptr;
        float4 b1 = *(const float4*)(Bptr + 4);
        Bptr += (size_t)16 * DIMC;
        As[sa_k+0][sa_m] = f2tf32(a0.x); As[sa_k+1][sa_m] = f2tf32(a0.y);
        As[sa_k+2][sa_m] = f2tf32(a0.z); As[sa_k+3][sa_m] = f2tf32(a0.w);
        As[sa_k+4][sa_m] = f2tf32(a1.x); As[sa_k+5][sa_m] = f2tf32(a1.y);
        As[sa_k+6][sa_m] = f2tf32(a1.z); As[sa_k+7][sa_m] = f2tf32(a1.w);
        *(uint4*)&Bs[sb_k][sb_n]   = make_uint4(f2tf32(b0.x), f2tf32(b0.y), f2tf32(b0.z), f2tf32(b0.w));
        *(uint4*)&Bs[sb_k][sb_n+4] = make_uint4(f2tf32(b1.x), f2tf32(b1.y), f2tf32(b1.z), f2tf32(b1.w));
        __syncthreads();
        #pragma unroll
        for (int ks = 0; ks < 2; ks++) {
            int kr = ks * 8 + (lane & 3);
            int mr = wm + (lane >> 2);
            int nr = wn + (lane >> 2);
            uint32_t af[4][4], bf[4][2];
            #pragma unroll
            for (int mt = 0; mt < 4; mt++) {
                af[mt][0] = As[kr][mr + mt*16];
                af[mt][1] = As[kr][mr + mt*16 + 8];
                af[mt][2] = As[kr+4][mr + mt*16];
                af[mt][3] = As[kr+4][mr + mt*16 + 8];
            }
            #pragma unroll
            for (int nt = 0; nt < 4; nt++) {
                bf[nt][0] = Bs[kr][nr + nt*8];
                bf[nt][1] = Bs[kr+4][nr + nt*8];
            }
            #pragma unroll
            for (int mt = 0; mt < 4; mt++)
                #pragma unroll
                for (int nt = 0; nt < 4; nt++)
                    MMA_TF32(c[mt][nt], af[mt], bf[nt]);
        }
        __syncthreads();
    }
    int col0 = n0 + wn + 2 * (lane & 3);
    int row0 = m0 + wm + (lane >> 2);
    #pragma unroll
    for (int nt = 0; nt < 4; nt++) {
        float b0v = bout[col0 + nt*8];
        float b1v = bout[col0 + nt*8 + 1];
        #pragma unroll
        for (int mt = 0; mt < 4; mt++) {
            float* Cp = out + (size_t)(row0 + mt*16) * DIMC + col0 + nt*8;
            *(float2*)Cp = make_float2(c[mt][nt][0] + b0v, c[mt][nt][1] + b1v);
            *(float2*)(Cp + (size_t)8 * DIMC) = make_float2(c[mt][nt][2] + b0v, c[mt][nt][3] + b1v);
        }
    }
}

// ============================================================ launch
extern "C" void kernel_launch(void* const* d_in, const int* in_sizes, int n_in,
                              void* d_out, int out_size) {
    const float* x       = (const float*)d_in[0];
    const float* ln_g    = (const float*)d_in[1];
    const float* ln_b    = (const float*)d_in[2];
    const float* Wq      = (const float*)d_in[3];
    const float* Wkv     = (const float*)d_in[4];
    const float* mixpre  = (const float*)d_in[5];
    const float* mixpost = (const float*)d_in[6];
    const float* Wout    = (const float*)d_in[7];
    const float* bout    = (const float*)d_in[8];
    float* out = (float*)d_out;

    cudaFuncSetAttribute(mixsoftmax_kernel,
                         cudaFuncAttributeMaxDynamicSharedMemorySize, NH * SEQ * 4);

    ln_kernel<<<NROWS, 256>>>(x, ln_g, ln_b);
    proj_mma_kernel<<<dim3(24, 32), 256>>>(Wq, Wkv);
    qk_mma_kernel<<<dim3(16, 16, 32), 256>>>();
    mixsoftmax_kernel<<<BQ * SEQ, 256, NH * SEQ * 4>>>(mixpre, mixpost);
    av_mma_kernel<<<dim3(16, 32), 256>>>();
    out_mma_kernel<<<dim3(8, 32), 256>>>(Wout, bout, out);
}